// round 15
// baseline (speedup 1.0000x reference)
#include <cuda_runtime.h>
#include <cuda_fp16.h>
#include <math.h>
#include <stdint.h>

#define BATCH   4096
#define D_MODEL 1024
#define NT      64
#define RANK    8
#define NR      512

// Scratch (device globals; g_pre zero-init + self-resetting)
__device__ __half g_Xh[(size_t)BATCH * D_MODEL];   // x as fp16
__device__ __half g_Vh[(size_t)NR * D_MODEL];      // V as fp16
__device__ __half g_Eh[(size_t)NT * D_MODEL];      // encoder as fp16
__device__ __half g_Yh[(size_t)BATCH * NR];        // gated Vx as fp16
__device__ __half g_Wth[(size_t)D_MODEL * NR];     // U^T as fp16
__device__ float  g_pre[(size_t)BATCH * NT];       // split-K accumulator

__device__ __forceinline__ void mma_f16(float c[4], const uint32_t a[4], const uint32_t b[2]) {
    asm volatile(
        "mma.sync.aligned.m16n8k16.row.col.f32.f16.f16.f32 "
        "{%0,%1,%2,%3}, {%4,%5,%6,%7}, {%8,%9}, {%0,%1,%2,%3};"
        : "+f"(c[0]), "+f"(c[1]), "+f"(c[2]), "+f"(c[3])
        : "r"(a[0]), "r"(a[1]), "r"(a[2]), "r"(a[3]), "r"(b[0]), "r"(b[1]));
}

__device__ __forceinline__ void cp16(void* smem_dst, const void* gmem_src) {
    uint32_t sa = (uint32_t)__cvta_generic_to_shared(smem_dst);
    asm volatile("cp.async.cg.shared.global [%0], [%1], 16;\n" :: "r"(sa), "l"(gmem_src));
}

#define LDSM4(d0, d1, d2, d3, addr)                                        \
    asm volatile("ldmatrix.sync.aligned.m8n8.x4.shared.b16 "               \
                 "{%0,%1,%2,%3}, [%4];"                                    \
                 : "=r"(d0), "=r"(d1), "=r"(d2), "=r"(d3) : "r"(addr))

__device__ __forceinline__ uint32_t h2u(__half2 h) {
    union { __half2 h; uint32_t u; } cvt;
    cvt.h = h;
    return cvt.u;
}

// ---------------------------------------------------------------------------
// fp16 NT GEMM, 3-stage cp.async, ldmatrix fragment loads.
// C[M,N] = A[M,K] @ B[N,K]^T.  BK = 32 halves, RW = 20 words/row (pad 4).
// MODE 1: v = (acc * gate[row][col/8]) -> g_Yh   A=g_Xh, B=g_Vh
// MODE 2: plain -> C (fp32)                       A=g_Yh, B=g_Wth
// MODE 3: split-K partial -> atomicAdd g_pre      A=g_Xh, B=g_Eh
// ---------------------------------------------------------------------------
template <int BM, int BN, int WY, int WX, int MINB, int MODE>
__global__ __launch_bounds__(WY * WX * 32, MINB)
void hgemm(float* __restrict__ Cg, int lda, int ldb, int Kloop, int ldc,
           const float* __restrict__ gate)
{
    constexpr int BK = 32;                 // halves
    constexpr int THREADS = WY * WX * 32;
    constexpr int WM = BM / WY;            // 64
    constexpr int WN = BN / WX;            // 32 or 16
    constexpr int MI = WM / 16;            // 4
    constexpr int NI = WN / 8;             // 4 or 2
    constexpr int RW = BK / 2 + 4;         // 20 words per row
    constexpr int SW = (BM + BN) * RW;     // words per stage
    constexpr int ACH = BM * 4 / THREADS;
    constexpr int BCH = BN * 4 / THREADS;

    extern __shared__ uint32_t smu[];

    const int tid  = threadIdx.x;
    const int wid  = tid >> 5;
    const int lane = tid & 31;
    const int wy   = wid / WX;
    const int wx   = wid % WX;
    const int lq   = lane >> 2;
    const int lr   = lane & 3;
    const int row0 = blockIdx.y * BM;
    const int col0 = (MODE == 3) ? 0 : blockIdx.x * BN;
    const int koff = (MODE == 3) ? blockIdx.x * Kloop : 0;

    const __half* A = (MODE == 2) ? g_Yh : g_Xh;
    const __half* B = (MODE == 1) ? g_Vh : ((MODE == 2) ? g_Wth : g_Eh);

    // ldmatrix per-lane geometry
    const int a_row = (lane & 7) + ((lane >> 3) & 1) * 8;
    const int a_col = (lane >> 4) * 4;
    const int b_row = (lane & 7) + (lane >> 4) * 8;
    const int b_col = ((lane >> 3) & 1) * 4;

    const uint32_t smem_u = (uint32_t)__cvta_generic_to_shared(smu);

    float acc[MI][NI][4];
#pragma unroll
    for (int mi = 0; mi < MI; mi++)
#pragma unroll
        for (int ni = 0; ni < NI; ni++)
#pragma unroll
            for (int j = 0; j < 4; j++) acc[mi][ni][j] = 0.0f;

    auto issue = [&](int t) {
        const int s = t % 3;
        uint32_t* as = smu + s * SW;
        uint32_t* bs = as + BM * RW;
        const int k0 = koff + t * BK;
#pragma unroll
        for (int j = 0; j < ACH; j++) {
            int ch = tid + j * THREADS;
            int r = ch >> 2, c4 = ch & 3;
            cp16(&as[r * RW + c4 * 4], &A[(size_t)(row0 + r) * lda + k0 + c4 * 8]);
        }
#pragma unroll
        for (int j = 0; j < BCH; j++) {
            int ch = tid + j * THREADS;
            int r = ch >> 2, c4 = ch & 3;
            cp16(&bs[r * RW + c4 * 4], &B[(size_t)(col0 + r) * ldb + k0 + c4 * 8]);
        }
        asm volatile("cp.async.commit_group;\n");
    };

    auto compute = [&](int s) {
        const uint32_t as_base = smem_u + s * SW * 4;
        const uint32_t bs_base = as_base + BM * RW * 4;
#pragma unroll
        for (int kk2 = 0; kk2 < BK / 2; kk2 += 8) {   // two k16 steps
            uint32_t af[MI][4], bf[NI][2];
#pragma unroll
            for (int mi = 0; mi < MI; mi++) {
                uint32_t addr = as_base +
                    (uint32_t)(((wy * WM + mi * 16 + a_row) * RW + kk2 + a_col) * 4);
                LDSM4(af[mi][0], af[mi][1], af[mi][2], af[mi][3], addr);
            }
#pragma unroll
            for (int p = 0; p < NI / 2; p++) {
                uint32_t addr = bs_base +
                    (uint32_t)(((wx * WN + p * 16 + b_row) * RW + kk2 + b_col) * 4);
                LDSM4(bf[2 * p][0], bf[2 * p][1], bf[2 * p + 1][0], bf[2 * p + 1][1], addr);
            }
#pragma unroll
            for (int mi = 0; mi < MI; mi++)
#pragma unroll
                for (int ni = 0; ni < NI; ni++)
                    mma_f16(acc[mi][ni], af[mi], bf[ni]);
        }
    };

    const int T = Kloop / BK;   // >= 4 everywhere

    issue(0);
    issue(1);
    asm volatile("cp.async.wait_group 1;\n");
    __syncthreads();

    for (int t = 0; t < T; t++) {
        if (t + 2 < T) issue(t + 2);
        compute(t % 3);
        if (t + 1 < T) {
            if (t + 2 < T) asm volatile("cp.async.wait_group 1;\n");
            else           asm volatile("cp.async.wait_group 0;\n");
            __syncthreads();
        }
    }

    // ---- epilogue ----
#pragma unroll
    for (int mi = 0; mi < MI; mi++) {
        int r0 = row0 + wy * WM + mi * 16 + lq;
#pragma unroll
        for (int ni = 0; ni < NI; ni++) {
            int c = col0 + wx * WN + ni * 8 + 2 * lr;
            float v0 = acc[mi][ni][0], v1 = acc[mi][ni][1];
            float v2 = acc[mi][ni][2], v3 = acc[mi][ni][3];
            if constexpr (MODE == 1) {
                int gc = (col0 + wx * WN + ni * 8) >> 3;
                float g0 = gate[(size_t)r0 * NT + gc];
                float g1 = gate[(size_t)(r0 + 8) * NT + gc];
                *(__half2*)&g_Yh[(size_t)r0 * ldc + c] =
                    __floats2half2_rn(v0 * g0, v1 * g0);
                *(__half2*)&g_Yh[(size_t)(r0 + 8) * ldc + c] =
                    __floats2half2_rn(v2 * g1, v3 * g1);
            } else if constexpr (MODE == 2) {
                *(float2*)&Cg[(size_t)r0 * ldc + c]       = make_float2(v0, v1);
                *(float2*)&Cg[(size_t)(r0 + 8) * ldc + c] = make_float2(v2, v3);
            } else {
                atomicAdd(&g_pre[(size_t)r0 * NT + c], v0);
                atomicAdd(&g_pre[(size_t)r0 * NT + c + 1], v1);
                atomicAdd(&g_pre[(size_t)(r0 + 8) * NT + c], v2);
                atomicAdd(&g_pre[(size_t)(r0 + 8) * NT + c + 1], v3);
            }
        }
    }
}

// ---------------------------------------------------------------------------
// prep: convert x/V/enc to fp16, coalesced U-transpose, Frobenius norms
// ---------------------------------------------------------------------------
#define PB_X   (BATCH * D_MODEL / 4 / 256)          /* 4096 */
#define PB_V   (NR * D_MODEL / 4 / 256)             /* 512  */
#define PB_E   (NT * D_MODEL / 4 / 256)             /* 64   */
#define PB_T   (D_MODEL / 16)                       /* 64 transpose blocks */
__global__ void prep(const float* __restrict__ x, const float* __restrict__ V,
                     const float* __restrict__ U, const float* __restrict__ enc,
                     float* __restrict__ fro)
{
    __shared__ uint32_t su[4096];     // 16 KB: transpose tile / reduction reuse
    int b = blockIdx.x;
    if (b < PB_X) {
        int i = b * 256 + threadIdx.x;
        float4 v = *(const float4*)&x[(size_t)i * 4];
        uint2 o = make_uint2(h2u(__floats2half2_rn(v.x, v.y)),
                             h2u(__floats2half2_rn(v.z, v.w)));
        *(uint2*)&g_Xh[(size_t)i * 4] = o;
    } else if (b < PB_X + PB_V) {
        int i = (b - PB_X) * 256 + threadIdx.x;
        float4 v = *(const float4*)&V[(size_t)i * 4];
        uint2 o = make_uint2(h2u(__floats2half2_rn(v.x, v.y)),
                             h2u(__floats2half2_rn(v.z, v.w)));
        *(uint2*)&g_Vh[(size_t)i * 4] = o;
    } else if (b < PB_X + PB_V + PB_E) {
        int i = (b - PB_X - PB_V) * 256 + threadIdx.x;
        float4 v = *(const float4*)&enc[(size_t)i * 4];
        uint2 o = make_uint2(h2u(__floats2half2_rn(v.x, v.y)),
                             h2u(__floats2half2_rn(v.z, v.w)));
        *(uint2*)&g_Eh[(size_t)i * 4] = o;
    } else if (b < PB_X + PB_V + PB_E + PB_T) {
        // coalesced transpose: d-band of 16 rows across all 64 transforms
        const int d0 = (b - PB_X - PB_V - PB_E) * 16;
        for (int p = threadIdx.x; p < 4096; p += 256) {
            int i = p * 2;
            int n = i >> 7;
            int j = i & 127;
            float2 v = *(const float2*)&U[(size_t)n * (D_MODEL * RANK) + d0 * 8 + j];
            int dd = j >> 3, r = j & 7;
            su[(dd * 512 + n * 8 + r) >> 1] = h2u(__floats2half2_rn(v.x, v.y));
        }
        __syncthreads();
        for (int p = threadIdx.x; p < 4096; p += 256) {
            int e = p * 2;
            int dd = e >> 9;
            int c = e & 511;
            *(uint32_t*)&g_Wth[(size_t)(d0 + dd) * NR + c] = su[p];
        }
    } else {
        // Frobenius norms
        float* ssu = (float*)su;
        float* ssv = ssu + 256;
        int n = b - PB_X - PB_V - PB_E - PB_T;
        float sU = 0.0f, sV = 0.0f;
        for (int i = threadIdx.x; i < D_MODEL * RANK; i += 256) {
            float u = U[(size_t)n * (D_MODEL * RANK) + i];
            float v = V[(size_t)n * (D_MODEL * RANK) + i];
            sU += u * u;
            sV += v * v;
        }
        ssu[threadIdx.x] = sU;
        ssv[threadIdx.x] = sV;
        __syncthreads();
        for (int s = 128; s > 0; s >>= 1) {
            if (threadIdx.x < s) {
                ssu[threadIdx.x] += ssu[threadIdx.x + s];
                ssv[threadIdx.x] += ssv[threadIdx.x + s];
            }
            __syncthreads();
        }
        if (threadIdx.x == 0)
            fro[n] = sqrtf(ssu[0]) * sqrtf(ssv[0]) * rsqrtf((float)(D_MODEL * RANK));
    }
}

// gate = relu(pre - bias); reset pre for next replay
__global__ void gate_relu(const float* __restrict__ bias, float* __restrict__ gate)
{
    int i = blockIdx.x * 256 + threadIdx.x;
    int c = (i * 4) & (NT - 1);
    float4 p = *(float4*)&g_pre[(size_t)i * 4];
    float4 b = *(const float4*)&bias[c];
    float4 o;
    float v0 = p.x - b.x, v1 = p.y - b.y, v2 = p.z - b.z, v3 = p.w - b.w;
    o.x = v0 > 0.f ? v0 : 0.f;  o.y = v1 > 0.f ? v1 : 0.f;
    o.z = v2 > 0.f ? v2 : 0.f;  o.w = v3 > 0.f ? v3 : 0.f;
    *(float4*)&gate[(size_t)i * 4] = o;
    *(float4*)&g_pre[(size_t)i * 4] = make_float4(0.f, 0.f, 0.f, 0.f);
}

extern "C" void kernel_launch(void* const* d_in, const int* in_sizes, int n_in,
                              void* d_out, int out_size)
{
    const float* x    = (const float*)d_in[0];
    const float* V    = (const float*)d_in[1];
    const float* U    = (const float*)d_in[2];
    const float* enc  = (const float*)d_in[3];
    const float* bias = (const float*)d_in[4];

    float* out  = (float*)d_out;
    float* gate = out + (size_t)BATCH * D_MODEL;
    float* fro  = gate + (size_t)BATCH * NT;

    constexpr int SM_P1 = 3 * (64 + 64) * 20 * 4;     // 30720
    constexpr int SM_BIG = 3 * (128 + 128) * 20 * 4;  // 61440

    cudaFuncSetAttribute(hgemm<64, 64, 1, 4, 4, 3>,
                         cudaFuncAttributeMaxDynamicSharedMemorySize, SM_P1);
    cudaFuncSetAttribute(hgemm<128, 128, 2, 4, 2, 1>,
                         cudaFuncAttributeMaxDynamicSharedMemorySize, SM_BIG);
    cudaFuncSetAttribute(hgemm<128, 128, 2, 4, 2, 2>,
                         cudaFuncAttributeMaxDynamicSharedMemorySize, SM_BIG);

    // prep: fp16 conversions, coalesced U^T, fro norms
    prep<<<PB_X + PB_V + PB_E + PB_T + NT, 256>>>(x, V, U, enc, fro);

    // Phase 1 (split-K x8): g_pre += x @ enc^T   [4096 x 64]  grid 512
    hgemm<64, 64, 1, 4, 4, 3><<<dim3(8, BATCH / 64), 128, SM_P1>>>(
        nullptr, D_MODEL, D_MODEL, 128, 0, nullptr);

    // Phase 1b: gate = relu(pre - bias), reset pre
    gate_relu<<<BATCH * NT / 4 / 256, 256>>>(bias, gate);

    // Phase 2: g_Yh = (x @ V^T) * gate  [4096 x 512]  grid 128 (128x128 tiles)
    hgemm<128, 128, 2, 4, 2, 1><<<dim3(NR / 128, BATCH / 128), 256, SM_BIG>>>(
        nullptr, D_MODEL, D_MODEL, D_MODEL, NR, gate);

    // Phase 3: out = g_Yh @ g_Wth^T   [4096 x 1024]  grid 256
    hgemm<128, 128, 2, 4, 2, 2><<<dim3(D_MODEL / 128, BATCH / 128), 256, SM_BIG>>>(
        out, NR, NR, NR, D_MODEL, nullptr);
}

// round 16
// speedup vs baseline: 1.0152x; 1.0152x over previous
#include <cuda_runtime.h>
#include <cuda_fp16.h>
#include <math.h>
#include <stdint.h>

#define BATCH   4096
#define D_MODEL 1024
#define NT      64
#define RANK    8
#define NR      512

// Scratch (device globals; g_pre zero-init + self-resetting)
__device__ __half g_Xh[(size_t)BATCH * D_MODEL];   // x as fp16
__device__ __half g_Vh[(size_t)NR * D_MODEL];      // V as fp16
__device__ __half g_Eh[(size_t)NT * D_MODEL];      // encoder as fp16
__device__ __half g_Yh[(size_t)BATCH * NR];        // gated Vx as fp16
__device__ __half g_Wth[(size_t)D_MODEL * NR];     // U^T as fp16
__device__ float  g_pre[(size_t)BATCH * NT];       // split-K accumulator

__device__ __forceinline__ void mma_f16(float c[4], const uint32_t a[4], const uint32_t b[2]) {
    asm volatile(
        "mma.sync.aligned.m16n8k16.row.col.f32.f16.f16.f32 "
        "{%0,%1,%2,%3}, {%4,%5,%6,%7}, {%8,%9}, {%0,%1,%2,%3};"
        : "+f"(c[0]), "+f"(c[1]), "+f"(c[2]), "+f"(c[3])
        : "r"(a[0]), "r"(a[1]), "r"(a[2]), "r"(a[3]), "r"(b[0]), "r"(b[1]));
}

__device__ __forceinline__ void cp16(void* smem_dst, const void* gmem_src) {
    uint32_t sa = (uint32_t)__cvta_generic_to_shared(smem_dst);
    asm volatile("cp.async.cg.shared.global [%0], [%1], 16;\n" :: "r"(sa), "l"(gmem_src));
}

#define LDSM4(d0, d1, d2, d3, addr)                                        \
    asm volatile("ldmatrix.sync.aligned.m8n8.x4.shared.b16 "               \
                 "{%0,%1,%2,%3}, [%4];"                                    \
                 : "=r"(d0), "=r"(d1), "=r"(d2), "=r"(d3) : "r"(addr))

__device__ __forceinline__ uint32_t h2u(__half2 h) {
    union { __half2 h; uint32_t u; } cvt;
    cvt.h = h;
    return cvt.u;
}

// ---------------------------------------------------------------------------
// fp16 NT GEMM, 3-stage cp.async, ldmatrix fragment loads.
// C[M,N] = A[M,K] @ B[N,K]^T.  BK = 32 halves, RW = 20 words/row (pad 4).
// MODE 1: v = (acc * gate[row][col/8]) -> g_Yh   A=g_Xh, B=g_Vh
// MODE 2: plain -> C (fp32)                       A=g_Yh, B=g_Wth
// MODE 3: split-K partial -> atomicAdd g_pre      A=g_Xh, B=g_Eh
// ---------------------------------------------------------------------------
template <int BM, int BN, int WY, int WX, int MINB, int MODE>
__global__ __launch_bounds__(WY * WX * 32, MINB)
void hgemm(float* __restrict__ Cg, int lda, int ldb, int Kloop, int ldc,
           const float* __restrict__ gate)
{
    constexpr int BK = 32;                 // halves
    constexpr int THREADS = WY * WX * 32;
    constexpr int WM = BM / WY;            // 64 or 32
    constexpr int WN = BN / WX;            // 32 or 16
    constexpr int MI = WM / 16;            // 4 or 2
    constexpr int NI = WN / 8;             // 4 or 2
    constexpr int RW = BK / 2 + 4;         // 20 words per row
    constexpr int SW = (BM + BN) * RW;     // words per stage
    constexpr int ACH = BM * 4 / THREADS;
    constexpr int BCH = BN * 4 / THREADS;

    extern __shared__ uint32_t smu[];

    const int tid  = threadIdx.x;
    const int wid  = tid >> 5;
    const int lane = tid & 31;
    const int wy   = wid / WX;
    const int wx   = wid % WX;
    const int lq   = lane >> 2;
    const int lr   = lane & 3;
    const int row0 = blockIdx.y * BM;
    const int col0 = (MODE == 3) ? 0 : blockIdx.x * BN;
    const int koff = (MODE == 3) ? blockIdx.x * Kloop : 0;

    const __half* A = (MODE == 2) ? g_Yh : g_Xh;
    const __half* B = (MODE == 1) ? g_Vh : ((MODE == 2) ? g_Wth : g_Eh);

    // ldmatrix per-lane geometry
    const int a_row = (lane & 7) + ((lane >> 3) & 1) * 8;
    const int a_col = (lane >> 4) * 4;
    const int b_row = (lane & 7) + (lane >> 4) * 8;
    const int b_col = ((lane >> 3) & 1) * 4;

    const uint32_t smem_u = (uint32_t)__cvta_generic_to_shared(smu);

    float acc[MI][NI][4];
#pragma unroll
    for (int mi = 0; mi < MI; mi++)
#pragma unroll
        for (int ni = 0; ni < NI; ni++)
#pragma unroll
            for (int j = 0; j < 4; j++) acc[mi][ni][j] = 0.0f;

    auto issue = [&](int t) {
        const int s = t % 3;
        uint32_t* as = smu + s * SW;
        uint32_t* bs = as + BM * RW;
        const int k0 = koff + t * BK;
#pragma unroll
        for (int j = 0; j < ACH; j++) {
            int ch = tid + j * THREADS;
            int r = ch >> 2, c4 = ch & 3;
            cp16(&as[r * RW + c4 * 4], &A[(size_t)(row0 + r) * lda + k0 + c4 * 8]);
        }
#pragma unroll
        for (int j = 0; j < BCH; j++) {
            int ch = tid + j * THREADS;
            int r = ch >> 2, c4 = ch & 3;
            cp16(&bs[r * RW + c4 * 4], &B[(size_t)(col0 + r) * ldb + k0 + c4 * 8]);
        }
        asm volatile("cp.async.commit_group;\n");
    };

    auto compute = [&](int s) {
        const uint32_t as_base = smem_u + s * SW * 4;
        const uint32_t bs_base = as_base + BM * RW * 4;
#pragma unroll
        for (int kk2 = 0; kk2 < BK / 2; kk2 += 8) {   // two k16 steps
            uint32_t af[MI][4], bf[NI][2];
#pragma unroll
            for (int mi = 0; mi < MI; mi++) {
                uint32_t addr = as_base +
                    (uint32_t)(((wy * WM + mi * 16 + a_row) * RW + kk2 + a_col) * 4);
                LDSM4(af[mi][0], af[mi][1], af[mi][2], af[mi][3], addr);
            }
#pragma unroll
            for (int p = 0; p < NI / 2; p++) {
                uint32_t addr = bs_base +
                    (uint32_t)(((wx * WN + p * 16 + b_row) * RW + kk2 + b_col) * 4);
                LDSM4(bf[2 * p][0], bf[2 * p][1], bf[2 * p + 1][0], bf[2 * p + 1][1], addr);
            }
#pragma unroll
            for (int mi = 0; mi < MI; mi++)
#pragma unroll
                for (int ni = 0; ni < NI; ni++)
                    mma_f16(acc[mi][ni], af[mi], bf[ni]);
        }
    };

    const int T = Kloop / BK;   // >= 4 everywhere

    issue(0);
    issue(1);
    asm volatile("cp.async.wait_group 1;\n");
    __syncthreads();

    for (int t = 0; t < T; t++) {
        if (t + 2 < T) issue(t + 2);
        compute(t % 3);
        if (t + 1 < T) {
            if (t + 2 < T) asm volatile("cp.async.wait_group 1;\n");
            else           asm volatile("cp.async.wait_group 0;\n");
            __syncthreads();
        }
    }

    // ---- epilogue ----
#pragma unroll
    for (int mi = 0; mi < MI; mi++) {
        int r0 = row0 + wy * WM + mi * 16 + lq;
#pragma unroll
        for (int ni = 0; ni < NI; ni++) {
            int c = col0 + wx * WN + ni * 8 + 2 * lr;
            float v0 = acc[mi][ni][0], v1 = acc[mi][ni][1];
            float v2 = acc[mi][ni][2], v3 = acc[mi][ni][3];
            if constexpr (MODE == 1) {
                int gc = (col0 + wx * WN + ni * 8) >> 3;
                float g0 = gate[(size_t)r0 * NT + gc];
                float g1 = gate[(size_t)(r0 + 8) * NT + gc];
                *(__half2*)&g_Yh[(size_t)r0 * ldc + c] =
                    __floats2half2_rn(v0 * g0, v1 * g0);
                *(__half2*)&g_Yh[(size_t)(r0 + 8) * ldc + c] =
                    __floats2half2_rn(v2 * g1, v3 * g1);
            } else if constexpr (MODE == 2) {
                *(float2*)&Cg[(size_t)r0 * ldc + c]       = make_float2(v0, v1);
                *(float2*)&Cg[(size_t)(r0 + 8) * ldc + c] = make_float2(v2, v3);
            } else {
                atomicAdd(&g_pre[(size_t)r0 * NT + c], v0);
                atomicAdd(&g_pre[(size_t)r0 * NT + c + 1], v1);
                atomicAdd(&g_pre[(size_t)(r0 + 8) * NT + c], v2);
                atomicAdd(&g_pre[(size_t)(r0 + 8) * NT + c + 1], v3);
            }
        }
    }
}

// ---------------------------------------------------------------------------
// prep: convert x/V/enc to fp16, coalesced U-transpose, Frobenius norms
// ---------------------------------------------------------------------------
#define PB_X   (BATCH * D_MODEL / 4 / 256)          /* 4096 */
#define PB_V   (NR * D_MODEL / 4 / 256)             /* 512  */
#define PB_E   (NT * D_MODEL / 4 / 256)             /* 64   */
#define PB_T   (D_MODEL / 16)                       /* 64 transpose blocks */
__global__ void prep(const float* __restrict__ x, const float* __restrict__ V,
                     const float* __restrict__ U, const float* __restrict__ enc,
                     float* __restrict__ fro)
{
    __shared__ uint32_t su[4096];     // 16 KB: transpose tile / reduction reuse
    int b = blockIdx.x;
    if (b < PB_X) {
        int i = b * 256 + threadIdx.x;
        float4 v = *(const float4*)&x[(size_t)i * 4];
        uint2 o = make_uint2(h2u(__floats2half2_rn(v.x, v.y)),
                             h2u(__floats2half2_rn(v.z, v.w)));
        *(uint2*)&g_Xh[(size_t)i * 4] = o;
    } else if (b < PB_X + PB_V) {
        int i = (b - PB_X) * 256 + threadIdx.x;
        float4 v = *(const float4*)&V[(size_t)i * 4];
        uint2 o = make_uint2(h2u(__floats2half2_rn(v.x, v.y)),
                             h2u(__floats2half2_rn(v.z, v.w)));
        *(uint2*)&g_Vh[(size_t)i * 4] = o;
    } else if (b < PB_X + PB_V + PB_E) {
        int i = (b - PB_X - PB_V) * 256 + threadIdx.x;
        float4 v = *(const float4*)&enc[(size_t)i * 4];
        uint2 o = make_uint2(h2u(__floats2half2_rn(v.x, v.y)),
                             h2u(__floats2half2_rn(v.z, v.w)));
        *(uint2*)&g_Eh[(size_t)i * 4] = o;
    } else if (b < PB_X + PB_V + PB_E + PB_T) {
        // coalesced transpose: d-band of 16 rows across all 64 transforms
        const int d0 = (b - PB_X - PB_V - PB_E) * 16;
        for (int p = threadIdx.x; p < 4096; p += 256) {
            int i = p * 2;
            int n = i >> 7;
            int j = i & 127;
            float2 v = *(const float2*)&U[(size_t)n * (D_MODEL * RANK) + d0 * 8 + j];
            int dd = j >> 3, r = j & 7;
            su[(dd * 512 + n * 8 + r) >> 1] = h2u(__floats2half2_rn(v.x, v.y));
        }
        __syncthreads();
        for (int p = threadIdx.x; p < 4096; p += 256) {
            int e = p * 2;
            int dd = e >> 9;
            int c = e & 511;
            *(uint32_t*)&g_Wth[(size_t)(d0 + dd) * NR + c] = su[p];
        }
    } else {
        // Frobenius norms
        float* ssu = (float*)su;
        float* ssv = ssu + 256;
        int n = b - PB_X - PB_V - PB_E - PB_T;
        float sU = 0.0f, sV = 0.0f;
        for (int i = threadIdx.x; i < D_MODEL * RANK; i += 256) {
            float u = U[(size_t)n * (D_MODEL * RANK) + i];
            float v = V[(size_t)n * (D_MODEL * RANK) + i];
            sU += u * u;
            sV += v * v;
        }
        ssu[threadIdx.x] = sU;
        ssv[threadIdx.x] = sV;
        __syncthreads();
        for (int s = 128; s > 0; s >>= 1) {
            if (threadIdx.x < s) {
                ssu[threadIdx.x] += ssu[threadIdx.x + s];
                ssv[threadIdx.x] += ssv[threadIdx.x + s];
            }
            __syncthreads();
        }
        if (threadIdx.x == 0)
            fro[n] = sqrtf(ssu[0]) * sqrtf(ssv[0]) * rsqrtf((float)(D_MODEL * RANK));
    }
}

// gate = relu(pre - bias); reset pre for next replay
__global__ void gate_relu(const float* __restrict__ bias, float* __restrict__ gate)
{
    int i = blockIdx.x * 256 + threadIdx.x;
    int c = (i * 4) & (NT - 1);
    float4 p = *(float4*)&g_pre[(size_t)i * 4];
    float4 b = *(const float4*)&bias[c];
    float4 o;
    float v0 = p.x - b.x, v1 = p.y - b.y, v2 = p.z - b.z, v3 = p.w - b.w;
    o.x = v0 > 0.f ? v0 : 0.f;  o.y = v1 > 0.f ? v1 : 0.f;
    o.z = v2 > 0.f ? v2 : 0.f;  o.w = v3 > 0.f ? v3 : 0.f;
    *(float4*)&gate[(size_t)i * 4] = o;
    *(float4*)&g_pre[(size_t)i * 4] = make_float4(0.f, 0.f, 0.f, 0.f);
}

extern "C" void kernel_launch(void* const* d_in, const int* in_sizes, int n_in,
                              void* d_out, int out_size)
{
    const float* x    = (const float*)d_in[0];
    const float* V    = (const float*)d_in[1];
    const float* U    = (const float*)d_in[2];
    const float* enc  = (const float*)d_in[3];
    const float* bias = (const float*)d_in[4];

    float* out  = (float*)d_out;
    float* gate = out + (size_t)BATCH * D_MODEL;
    float* fro  = gate + (size_t)BATCH * NT;

    constexpr int SM_P1 = 3 * (64 + 64) * 20 * 4;     // 30720
    constexpr int SM_P2 = 3 * (64 + 128) * 20 * 4;    // 46080
    constexpr int SM_P3 = 3 * (128 + 128) * 20 * 4;   // 61440

    cudaFuncSetAttribute(hgemm<64, 64, 1, 4, 4, 3>,
                         cudaFuncAttributeMaxDynamicSharedMemorySize, SM_P1);
    cudaFuncSetAttribute(hgemm<64, 128, 2, 4, 2, 1>,
                         cudaFuncAttributeMaxDynamicSharedMemorySize, SM_P2);
    cudaFuncSetAttribute(hgemm<128, 128, 2, 4, 2, 2>,
                         cudaFuncAttributeMaxDynamicSharedMemorySize, SM_P3);

    // prep: fp16 conversions, coalesced U^T, fro norms
    prep<<<PB_X + PB_V + PB_E + PB_T + NT, 256>>>(x, V, U, enc, fro);

    // Phase 1 (split-K x8): g_pre += x @ enc^T   [4096 x 64]  grid 512
    hgemm<64, 64, 1, 4, 4, 3><<<dim3(8, BATCH / 64), 128, SM_P1>>>(
        nullptr, D_MODEL, D_MODEL, 128, 0, nullptr);

    // Phase 1b: gate = relu(pre - bias), reset pre
    gate_relu<<<BATCH * NT / 4 / 256, 256>>>(bias, gate);

    // Phase 2: g_Yh = (x @ V^T) * gate  [4096 x 512]  grid 256, 8 warps/CTA
    hgemm<64, 128, 2, 4, 2, 1><<<dim3(NR / 128, BATCH / 64), 256, SM_P2>>>(
        nullptr, D_MODEL, D_MODEL, D_MODEL, NR, gate);

    // Phase 3: out = g_Yh @ g_Wth^T   [4096 x 1024]  grid 256
    hgemm<128, 128, 2, 4, 2, 2><<<dim3(D_MODEL / 128, BATCH / 128), 256, SM_P3>>>(
        out, NR, NR, NR, D_MODEL, nullptr);
}

// round 17
// speedup vs baseline: 1.1063x; 1.0897x over previous
#include <cuda_runtime.h>
#include <cuda_fp16.h>
#include <math.h>
#include <stdint.h>

#define BATCH   4096
#define D_MODEL 1024
#define NT      64
#define RANK    8
#define NR      512

// Scratch (device globals; g_pre zero-init + self-resetting)
__device__ __half g_Xh[(size_t)BATCH * D_MODEL];   // x as fp16
__device__ __half g_Vh[(size_t)NR * D_MODEL];      // V as fp16
__device__ __half g_Eh[(size_t)NT * D_MODEL];      // encoder as fp16
__device__ __half g_Yh[(size_t)BATCH * NR];        // gated Vx as fp16
__device__ __half g_Wth[(size_t)D_MODEL * NR];     // U^T as fp16
__device__ float  g_pre[(size_t)BATCH * NT];       // split-K accumulator

__device__ __forceinline__ void mma_f16(float c[4], const uint32_t a[4], const uint32_t b[2]) {
    asm volatile(
        "mma.sync.aligned.m16n8k16.row.col.f32.f16.f16.f32 "
        "{%0,%1,%2,%3}, {%4,%5,%6,%7}, {%8,%9}, {%0,%1,%2,%3};"
        : "+f"(c[0]), "+f"(c[1]), "+f"(c[2]), "+f"(c[3])
        : "r"(a[0]), "r"(a[1]), "r"(a[2]), "r"(a[3]), "r"(b[0]), "r"(b[1]));
}

__device__ __forceinline__ void cp16(void* smem_dst, const void* gmem_src) {
    uint32_t sa = (uint32_t)__cvta_generic_to_shared(smem_dst);
    asm volatile("cp.async.cg.shared.global [%0], [%1], 16;\n" :: "r"(sa), "l"(gmem_src));
}

#define LDSM4(d0, d1, d2, d3, addr)                                        \
    asm volatile("ldmatrix.sync.aligned.m8n8.x4.shared.b16 "               \
                 "{%0,%1,%2,%3}, [%4];"                                    \
                 : "=r"(d0), "=r"(d1), "=r"(d2), "=r"(d3) : "r"(addr))

__device__ __forceinline__ uint32_t h2u(__half2 h) {
    union { __half2 h; uint32_t u; } cvt;
    cvt.h = h;
    return cvt.u;
}

// ---------------------------------------------------------------------------
// fp16 NT GEMM, 3-stage cp.async, ldmatrix fragment loads, templated BK.
// C[M,N] = A[M,K] @ B[N,K]^T.  RW = BK/2 + 4 words/row (stride coprime to 8
// 16B-segments -> conflict-free LDSM and cp.async STS).
// MODE 1: v = (acc * gate[row][col/8]) -> g_Yh   A=g_Xh, B=g_Vh
// MODE 2: plain -> C (fp32)                       A=g_Yh, B=g_Wth
// MODE 3: split-K partial -> atomicAdd g_pre      A=g_Xh, B=g_Eh
// ---------------------------------------------------------------------------
template <int BM, int BN, int BK, int WY, int WX, int MINB, int MODE>
__global__ __launch_bounds__(WY * WX * 32, MINB)
void hgemm(float* __restrict__ Cg, int lda, int ldb, int Kloop, int ldc,
           const float* __restrict__ gate)
{
    constexpr int THREADS = WY * WX * 32;
    constexpr int WM = BM / WY;            // 64
    constexpr int WN = BN / WX;            // 32 or 16
    constexpr int MI = WM / 16;            // 4
    constexpr int NI = WN / 8;             // 4 or 2
    constexpr int RW = BK / 2 + 4;         // words per row
    constexpr int SW = (BM + BN) * RW;     // words per stage
    constexpr int CPR = BK / 8;            // 16B chunks per row
    constexpr int ACH = BM * CPR / THREADS;
    constexpr int BCH = BN * CPR / THREADS;

    extern __shared__ uint32_t smu[];

    const int tid  = threadIdx.x;
    const int wid  = tid >> 5;
    const int lane = tid & 31;
    const int wy   = wid / WX;
    const int wx   = wid % WX;
    const int lq   = lane >> 2;
    const int lr   = lane & 3;
    const int row0 = blockIdx.y * BM;
    const int col0 = (MODE == 3) ? 0 : blockIdx.x * BN;
    const int koff = (MODE == 3) ? blockIdx.x * Kloop : 0;

    const __half* A = (MODE == 2) ? g_Yh : g_Xh;
    const __half* B = (MODE == 1) ? g_Vh : ((MODE == 2) ? g_Wth : g_Eh);

    // ldmatrix per-lane geometry
    const int a_row = (lane & 7) + ((lane >> 3) & 1) * 8;
    const int a_col = (lane >> 4) * 4;
    const int b_row = (lane & 7) + (lane >> 4) * 8;
    const int b_col = ((lane >> 3) & 1) * 4;

    const uint32_t smem_u = (uint32_t)__cvta_generic_to_shared(smu);

    float acc[MI][NI][4];
#pragma unroll
    for (int mi = 0; mi < MI; mi++)
#pragma unroll
        for (int ni = 0; ni < NI; ni++)
#pragma unroll
            for (int j = 0; j < 4; j++) acc[mi][ni][j] = 0.0f;

    auto issue = [&](int t) {
        const int s = t % 3;
        uint32_t* as = smu + s * SW;
        uint32_t* bs = as + BM * RW;
        const int k0 = koff + t * BK;
#pragma unroll
        for (int j = 0; j < ACH; j++) {
            int ch = tid + j * THREADS;
            int r = ch / CPR, c4 = ch % CPR;
            cp16(&as[r * RW + c4 * 4], &A[(size_t)(row0 + r) * lda + k0 + c4 * 8]);
        }
#pragma unroll
        for (int j = 0; j < BCH; j++) {
            int ch = tid + j * THREADS;
            int r = ch / CPR, c4 = ch % CPR;
            cp16(&bs[r * RW + c4 * 4], &B[(size_t)(col0 + r) * ldb + k0 + c4 * 8]);
        }
        asm volatile("cp.async.commit_group;\n");
    };

    auto compute = [&](int s) {
        const uint32_t as_base = smem_u + s * SW * 4;
        const uint32_t bs_base = as_base + BM * RW * 4;
#pragma unroll
        for (int kk2 = 0; kk2 < BK / 2; kk2 += 8) {   // k16 steps
            uint32_t af[MI][4], bf[NI][2];
#pragma unroll
            for (int mi = 0; mi < MI; mi++) {
                uint32_t addr = as_base +
                    (uint32_t)(((wy * WM + mi * 16 + a_row) * RW + kk2 + a_col) * 4);
                LDSM4(af[mi][0], af[mi][1], af[mi][2], af[mi][3], addr);
            }
#pragma unroll
            for (int p = 0; p < NI / 2; p++) {
                uint32_t addr = bs_base +
                    (uint32_t)(((wx * WN + p * 16 + b_row) * RW + kk2 + b_col) * 4);
                LDSM4(bf[2 * p][0], bf[2 * p][1], bf[2 * p + 1][0], bf[2 * p + 1][1], addr);
            }
#pragma unroll
            for (int mi = 0; mi < MI; mi++)
#pragma unroll
                for (int ni = 0; ni < NI; ni++)
                    mma_f16(acc[mi][ni], af[mi], bf[ni]);
        }
    };

    const int T = Kloop / BK;   // >= 4 everywhere (p1: 4, p2: 16, p3: 8)

    issue(0);
    issue(1);
    asm volatile("cp.async.wait_group 1;\n");
    __syncthreads();

    for (int t = 0; t < T; t++) {
        if (t + 2 < T) issue(t + 2);
        compute(t % 3);
        if (t + 1 < T) {
            if (t + 2 < T) asm volatile("cp.async.wait_group 1;\n");
            else           asm volatile("cp.async.wait_group 0;\n");
            __syncthreads();
        }
    }

    // ---- epilogue ----
#pragma unroll
    for (int mi = 0; mi < MI; mi++) {
        int r0 = row0 + wy * WM + mi * 16 + lq;
#pragma unroll
        for (int ni = 0; ni < NI; ni++) {
            int c = col0 + wx * WN + ni * 8 + 2 * lr;
            float v0 = acc[mi][ni][0], v1 = acc[mi][ni][1];
            float v2 = acc[mi][ni][2], v3 = acc[mi][ni][3];
            if constexpr (MODE == 1) {
                int gc = (col0 + wx * WN + ni * 8) >> 3;
                float g0 = gate[(size_t)r0 * NT + gc];
                float g1 = gate[(size_t)(r0 + 8) * NT + gc];
                *(__half2*)&g_Yh[(size_t)r0 * ldc + c] =
                    __floats2half2_rn(v0 * g0, v1 * g0);
                *(__half2*)&g_Yh[(size_t)(r0 + 8) * ldc + c] =
                    __floats2half2_rn(v2 * g1, v3 * g1);
            } else if constexpr (MODE == 2) {
                *(float2*)&Cg[(size_t)r0 * ldc + c]       = make_float2(v0, v1);
                *(float2*)&Cg[(size_t)(r0 + 8) * ldc + c] = make_float2(v2, v3);
            } else {
                atomicAdd(&g_pre[(size_t)r0 * NT + c], v0);
                atomicAdd(&g_pre[(size_t)r0 * NT + c + 1], v1);
                atomicAdd(&g_pre[(size_t)(r0 + 8) * NT + c], v2);
                atomicAdd(&g_pre[(size_t)(r0 + 8) * NT + c + 1], v3);
            }
        }
    }
}

// ---------------------------------------------------------------------------
// prep: convert x/V/enc to fp16, coalesced U-transpose, Frobenius norms
// ---------------------------------------------------------------------------
#define PB_X   (BATCH * D_MODEL / 4 / 256)          /* 4096 */
#define PB_V   (NR * D_MODEL / 4 / 256)             /* 512  */
#define PB_E   (NT * D_MODEL / 4 / 256)             /* 64   */
#define PB_T   (D_MODEL / 16)                       /* 64 transpose blocks */
__global__ void prep(const float* __restrict__ x, const float* __restrict__ V,
                     const float* __restrict__ U, const float* __restrict__ enc,
                     float* __restrict__ fro)
{
    __shared__ uint32_t su[4096];     // 16 KB: transpose tile / reduction reuse
    int b = blockIdx.x;
    if (b < PB_X) {
        int i = b * 256 + threadIdx.x;
        float4 v = *(const float4*)&x[(size_t)i * 4];
        uint2 o = make_uint2(h2u(__floats2half2_rn(v.x, v.y)),
                             h2u(__floats2half2_rn(v.z, v.w)));
        *(uint2*)&g_Xh[(size_t)i * 4] = o;
    } else if (b < PB_X + PB_V) {
        int i = (b - PB_X) * 256 + threadIdx.x;
        float4 v = *(const float4*)&V[(size_t)i * 4];
        uint2 o = make_uint2(h2u(__floats2half2_rn(v.x, v.y)),
                             h2u(__floats2half2_rn(v.z, v.w)));
        *(uint2*)&g_Vh[(size_t)i * 4] = o;
    } else if (b < PB_X + PB_V + PB_E) {
        int i = (b - PB_X - PB_V) * 256 + threadIdx.x;
        float4 v = *(const float4*)&enc[(size_t)i * 4];
        uint2 o = make_uint2(h2u(__floats2half2_rn(v.x, v.y)),
                             h2u(__floats2half2_rn(v.z, v.w)));
        *(uint2*)&g_Eh[(size_t)i * 4] = o;
    } else if (b < PB_X + PB_V + PB_E + PB_T) {
        // coalesced transpose: d-band of 16 rows across all 64 transforms
        const int d0 = (b - PB_X - PB_V - PB_E) * 16;
        for (int p = threadIdx.x; p < 4096; p += 256) {
            int i = p * 2;
            int n = i >> 7;
            int j = i & 127;
            float2 v = *(const float2*)&U[(size_t)n * (D_MODEL * RANK) + d0 * 8 + j];
            int dd = j >> 3, r = j & 7;
            su[(dd * 512 + n * 8 + r) >> 1] = h2u(__floats2half2_rn(v.x, v.y));
        }
        __syncthreads();
        for (int p = threadIdx.x; p < 4096; p += 256) {
            int e = p * 2;
            int dd = e >> 9;
            int c = e & 511;
            *(uint32_t*)&g_Wth[(size_t)(d0 + dd) * NR + c] = su[p];
        }
    } else {
        // Frobenius norms
        float* ssu = (float*)su;
        float* ssv = ssu + 256;
        int n = b - PB_X - PB_V - PB_E - PB_T;
        float sU = 0.0f, sV = 0.0f;
        for (int i = threadIdx.x; i < D_MODEL * RANK; i += 256) {
            float u = U[(size_t)n * (D_MODEL * RANK) + i];
            float v = V[(size_t)n * (D_MODEL * RANK) + i];
            sU += u * u;
            sV += v * v;
        }
        ssu[threadIdx.x] = sU;
        ssv[threadIdx.x] = sV;
        __syncthreads();
        for (int s = 128; s > 0; s >>= 1) {
            if (threadIdx.x < s) {
                ssu[threadIdx.x] += ssu[threadIdx.x + s];
                ssv[threadIdx.x] += ssv[threadIdx.x + s];
            }
            __syncthreads();
        }
        if (threadIdx.x == 0)
            fro[n] = sqrtf(ssu[0]) * sqrtf(ssv[0]) * rsqrtf((float)(D_MODEL * RANK));
    }
}

// gate = relu(pre - bias); reset pre for next replay
__global__ void gate_relu(const float* __restrict__ bias, float* __restrict__ gate)
{
    int i = blockIdx.x * 256 + threadIdx.x;
    int c = (i * 4) & (NT - 1);
    float4 p = *(float4*)&g_pre[(size_t)i * 4];
    float4 b = *(const float4*)&bias[c];
    float4 o;
    float v0 = p.x - b.x, v1 = p.y - b.y, v2 = p.z - b.z, v3 = p.w - b.w;
    o.x = v0 > 0.f ? v0 : 0.f;  o.y = v1 > 0.f ? v1 : 0.f;
    o.z = v2 > 0.f ? v2 : 0.f;  o.w = v3 > 0.f ? v3 : 0.f;
    *(float4*)&gate[(size_t)i * 4] = o;
    *(float4*)&g_pre[(size_t)i * 4] = make_float4(0.f, 0.f, 0.f, 0.f);
}

extern "C" void kernel_launch(void* const* d_in, const int* in_sizes, int n_in,
                              void* d_out, int out_size)
{
    const float* x    = (const float*)d_in[0];
    const float* V    = (const float*)d_in[1];
    const float* U    = (const float*)d_in[2];
    const float* enc  = (const float*)d_in[3];
    const float* bias = (const float*)d_in[4];

    float* out  = (float*)d_out;
    float* gate = out + (size_t)BATCH * D_MODEL;
    float* fro  = gate + (size_t)BATCH * NT;

    constexpr int SM_P1 = 3 * (64 + 64) * 20 * 4;     // 30720  (BK=32)
    constexpr int SM_P2 = 3 * (64 + 128) * 36 * 4;    // 82944  (BK=64)
    constexpr int SM_P3 = 3 * (128 + 128) * 36 * 4;   // 110592 (BK=64)

    cudaFuncSetAttribute(hgemm<64, 64, 32, 1, 4, 4, 3>,
                         cudaFuncAttributeMaxDynamicSharedMemorySize, SM_P1);
    cudaFuncSetAttribute(hgemm<64, 128, 64, 1, 4, 4, 1>,
                         cudaFuncAttributeMaxDynamicSharedMemorySize, SM_P2);
    cudaFuncSetAttribute(hgemm<128, 128, 64, 2, 4, 2, 2>,
                         cudaFuncAttributeMaxDynamicSharedMemorySize, SM_P3);

    // prep: fp16 conversions, coalesced U^T, fro norms
    prep<<<PB_X + PB_V + PB_E + PB_T + NT, 256>>>(x, V, U, enc, fro);

    // Phase 1 (split-K x8): g_pre += x @ enc^T   [4096 x 64]  grid 512
    hgemm<64, 64, 32, 1, 4, 4, 3><<<dim3(8, BATCH / 64), 128, SM_P1>>>(
        nullptr, D_MODEL, D_MODEL, 128, 0, nullptr);

    // Phase 1b: gate = relu(pre - bias), reset pre
    gate_relu<<<BATCH * NT / 4 / 256, 256>>>(bias, gate);

    // Phase 2: g_Yh = (x @ V^T) * gate  [4096 x 512]  grid 256, BK=64
    hgemm<64, 128, 64, 1, 4, 4, 1><<<dim3(NR / 128, BATCH / 64), 128, SM_P2>>>(
        nullptr, D_MODEL, D_MODEL, D_MODEL, NR, gate);

    // Phase 3: out = g_Yh @ g_Wth^T   [4096 x 1024]  grid 256, BK=64
    hgemm<128, 128, 64, 2, 4, 2, 2><<<dim3(D_MODEL / 128, BATCH / 128), 256, SM_P3>>>(
        out, NR, NR, NR, D_MODEL, nullptr);
}